// round 2
// baseline (speedup 1.0000x reference)
#include <cuda_runtime.h>
#include <cstdint>

#define S_SUBJ   4
#define B_BATCH  64
#define K_VOX    40000
#define OUT_DIMN 768
#define V_VOX    (64*64*48)

#define OTB     256          // outputs per block (= threads)
#define MT      16           // samples per block tile
#define KSPLIT  25           // K split factor
#define KCHUNK  1600         // 40000 / 25
#define KC      64           // smem K chunk (floats)
#define NITER   (KCHUNK/KC)  // 25

// -------- device scratch (allocation-free per harness rules) --------
__device__ float g_G[(size_t)B_BATCH * K_VOX];   // gathered voxels, [slot][k]
__device__ int   g_subj[B_BATCH];                // subject per original sample
__device__ int   g_order[B_BATCH];               // slot -> original sample index
__device__ int   g_slotsubj[B_BATCH];            // slot -> subject
__device__ int   g_off[S_SUBJ + 1];              // subject -> slot range

// -------- 1) grouping + dtype detection --------
__global__ void setup_kernel(const void* idp) {
    if (threadIdx.x != 0) return;
    const int* w = (const int*)idp;
    // int64 detection: values < 4, so high words are all zero for int64 input.
    bool is64 = true;
    for (int i = 1; i < B_BATCH; i += 2) {
        if (w[i] != 0) { is64 = false; break; }
    }
    int subj[B_BATCH];
    for (int b = 0; b < B_BATCH; b++) {
        int s = is64 ? w[2 * b] : w[b];
        subj[b] = s;
        g_subj[b] = s;
    }
    int cnt[S_SUBJ];
    for (int s = 0; s < S_SUBJ; s++) cnt[s] = 0;
    for (int b = 0; b < B_BATCH; b++) cnt[subj[b]]++;
    int off = 0, pos[S_SUBJ];
    for (int s = 0; s < S_SUBJ; s++) { g_off[s] = off; pos[s] = off; off += cnt[s]; }
    g_off[S_SUBJ] = off;
    for (int b = 0; b < B_BATCH; b++) {
        int s = subj[b];
        int p = pos[s]++;
        g_order[p] = b;
        g_slotsubj[p] = s;
    }
}

// -------- 2) out = bias[subj[b]] --------
__global__ void init_out_kernel(float* out, const float* bias) {
    int i = blockIdx.x * blockDim.x + threadIdx.x;
    if (i >= B_BATCH * OUT_DIMN) return;
    int b = i / OUT_DIMN;
    int o = i - b * OUT_DIMN;
    out[i] = bias[g_subj[b] * OUT_DIMN + o];
}

// -------- 3) gather: G[slot][k] = fmri[order[slot]][idx[subj][k]] --------
__global__ void gather_kernel(const float* __restrict__ fmri, const int* __restrict__ idx) {
    int slot = blockIdx.y;
    int k = blockIdx.x * blockDim.x + threadIdx.x;
    if (k >= K_VOX) return;
    int b = g_order[slot];
    int s = g_slotsubj[slot];
    g_G[(size_t)slot * K_VOX + k] = fmri[(size_t)b * V_VOX + idx[s * K_VOX + k]];
}

// -------- packed fp32x2 FMA (Blackwell-only PTX) --------
__device__ __forceinline__ unsigned long long fma2(unsigned long long a,
                                                   unsigned long long b,
                                                   unsigned long long c) {
    unsigned long long d;
    asm("fma.rn.f32x2 %0, %1, %2, %3;" : "=l"(d) : "l"(a), "l"(b), "l"(c));
    return d;
}

// -------- templated GEMM body: MR = padded row count (4/8/12/16) --------
template <int MR>
__device__ __forceinline__ void gemm_body(float* gs, const float4* gp, float* gdst,
                                          const ulonglong2* __restrict__ wp,
                                          int rows, int off, int mtile, int o,
                                          float* __restrict__ out) {
    unsigned long long acc[MR];
#pragma unroll
    for (int m = 0; m < MR; m++) acc[m] = 0ULL;

    float4 gpre = *gp;   // staged G prefetch (1 float4/thread covers 16x64 tile)

    for (int it = 0; it < NITER; it++) {
        __syncthreads();
        *(float4*)gdst = gpre;
        __syncthreads();
        if (it + 1 < NITER) gpre = *(const float4*)((const float*)gp + (it + 1) * KC);

        const ulonglong2* w = wp + it * (KC / 4);
#pragma unroll 4
        for (int kb = 0; kb < KC / 4; kb++) {
            ulonglong2 wv = w[kb];
#pragma unroll
            for (int m = 0; m < MR; m++) {
                ulonglong2 gv = *(const ulonglong2*)&gs[m * KC + kb * 4];  // broadcast
                acc[m] = fma2(gv.x, wv.x, acc[m]);
                acc[m] = fma2(gv.y, wv.y, acc[m]);
            }
        }
    }

    // epilogue: fold f32x2 halves, accumulate across K-splits
#pragma unroll
    for (int m = 0; m < MR; m++) {
        if (m < rows) {
            int b = g_order[off + mtile + m];
            unsigned long long a = acc[m];
            float lo = __uint_as_float((unsigned)(a & 0xffffffffULL));
            float hi = __uint_as_float((unsigned)(a >> 32));
            atomicAdd(&out[b * OUT_DIMN + o], lo + hi);
        }
    }
}

// -------- 4) grouped GEMM: out[b][o] += G[slot] . Wt[s][o] --------
__global__ void __launch_bounds__(256, 3) gemm_kernel(const float* __restrict__ Wt,
                                                      float* __restrict__ out) {
    __shared__ __align__(16) float gs[MT * KC];  // 4 KB

    int tid = threadIdx.x;
    int s = blockIdx.y >> 2;
    int mtile = (blockIdx.y & 3) * MT;
    int off = g_off[s];
    int count = g_off[s + 1] - off;
    int rows = count - mtile;
    if (rows <= 0) return;
    if (rows > MT) rows = MT;

    int o = blockIdx.x * OTB + tid;
    size_t k0 = (size_t)blockIdx.z * KCHUNK;

    const ulonglong2* wp =
        (const ulonglong2*)(Wt + ((size_t)(s * OUT_DIMN + o)) * K_VOX + k0);

    // staging map: thread t -> (row t>>4, 4 floats at (t&15)*4)
    int srow = tid >> 4;
    int scol = (tid & 15) * 4;
    int mglob = mtile + srow;
    int slot = off + (mglob < count ? mglob : count - 1);  // clamp padded rows
    const float4* gp = (const float4*)(g_G + (size_t)slot * K_VOX + k0 + scol);
    float* gdst = &gs[srow * KC + scol];

    int mq = (rows + 3) >> 2;  // 1..4 groups of 4
    switch (mq) {
        case 1: gemm_body<4>(gs, gp, gdst, wp, rows, off, mtile, o, out); break;
        case 2: gemm_body<8>(gs, gp, gdst, wp, rows, off, mtile, o, out); break;
        case 3: gemm_body<12>(gs, gp, gdst, wp, rows, off, mtile, o, out); break;
        default: gemm_body<16>(gs, gp, gdst, wp, rows, off, mtile, o, out); break;
    }
}

extern "C" void kernel_launch(void* const* d_in, const int* in_sizes, int n_in,
                              void* d_out, int out_size) {
    (void)in_sizes; (void)n_in; (void)out_size;
    const void*  idp  = d_in[0];                 // id_batch (int64 or int32)
    const float* fmri = (const float*)d_in[1];   // [B, D, H, W]
    const int*   idx  = (const int*)d_in[2];     // [S, K]
    const float* Wt   = (const float*)d_in[3];   // [S, OUT, K]
    const float* bias = (const float*)d_in[4];   // [S, OUT]
    float* out = (float*)d_out;                  // [B, 1, OUT]

    setup_kernel<<<1, 32>>>(idp);
    init_out_kernel<<<(B_BATCH * OUT_DIMN + 255) / 256, 256>>>(out, bias);
    gather_kernel<<<dim3((K_VOX + 255) / 256, B_BATCH), 256>>>(fmri, idx);
    gemm_kernel<<<dim3(OUT_DIMN / OTB, 16, KSPLIT), 256>>>(Wt, out);
}

// round 3
// speedup vs baseline: 1.3651x; 1.3651x over previous
#include <cuda_runtime.h>
#include <cstdint>

#define S_SUBJ   4
#define B_BATCH  64
#define K_VOX    40000
#define OUT_DIMN 768
#define V_VOX    (64*64*48)

#define OT      128          // outputs per block tile
#define MT      16           // samples per block tile
#define KSPLIT  25           // K split factor
#define KCHUNK  1600         // 40000 / 25
#define KC      32           // smem K chunk (floats)
#define NITER   (KCHUNK/KC)  // 50

// -------- device scratch (allocation-free per harness rules) --------
__device__ float g_G[(size_t)B_BATCH * K_VOX];   // gathered voxels, [slot][k]
__device__ int   g_subj[B_BATCH];                // subject per original sample
__device__ int   g_order[B_BATCH];               // slot -> original sample index
__device__ int   g_slotsubj[B_BATCH];            // slot -> subject
__device__ int   g_off[S_SUBJ + 1];              // subject -> slot range

// -------- 1) grouping + dtype detection --------
__global__ void setup_kernel(const void* idp) {
    if (threadIdx.x != 0) return;
    const int* w = (const int*)idp;
    // int64 detection: ids < 4, so high words are all zero for int64 input.
    bool is64 = true;
    for (int i = 1; i < B_BATCH; i += 2) {
        if (w[i] != 0) { is64 = false; break; }
    }
    int subj[B_BATCH];
    for (int b = 0; b < B_BATCH; b++) {
        int s = is64 ? w[2 * b] : w[b];
        subj[b] = s;
        g_subj[b] = s;
    }
    int cnt[S_SUBJ];
    for (int s = 0; s < S_SUBJ; s++) cnt[s] = 0;
    for (int b = 0; b < B_BATCH; b++) cnt[subj[b]]++;
    int off = 0, pos[S_SUBJ];
    for (int s = 0; s < S_SUBJ; s++) { g_off[s] = off; pos[s] = off; off += cnt[s]; }
    g_off[S_SUBJ] = off;
    for (int b = 0; b < B_BATCH; b++) {
        int s = subj[b];
        int p = pos[s]++;
        g_order[p] = b;
        g_slotsubj[p] = s;
    }
}

// -------- 2) out = bias[subj[b]] --------
__global__ void init_out_kernel(float* out, const float* bias) {
    int i = blockIdx.x * blockDim.x + threadIdx.x;
    if (i >= B_BATCH * OUT_DIMN) return;
    int b = i / OUT_DIMN;
    int o = i - b * OUT_DIMN;
    out[i] = bias[g_subj[b] * OUT_DIMN + o];
}

// -------- 3) gather: G[slot][k] = fmri[order[slot]][idx[subj][k]] --------
__global__ void gather_kernel(const float* __restrict__ fmri, const int* __restrict__ idx) {
    int slot = blockIdx.y;
    int k = blockIdx.x * blockDim.x + threadIdx.x;
    if (k >= K_VOX) return;
    int b = g_order[slot];
    int s = g_slotsubj[slot];
    g_G[(size_t)slot * K_VOX + k] = fmri[(size_t)b * V_VOX + idx[s * K_VOX + k]];
}

// -------- packed fp32x2 FMA (Blackwell-only PTX) --------
__device__ __forceinline__ unsigned long long fma2(unsigned long long a,
                                                   unsigned long long b,
                                                   unsigned long long c) {
    unsigned long long d;
    asm("fma.rn.f32x2 %0, %1, %2, %3;" : "=l"(d) : "l"(a), "l"(b), "l"(c));
    return d;
}

// -------- 4) grouped GEMM: out[b][o] += G[slot] . Wt[s][o] --------
// Block: 256 threads, tile OT=128 outputs x MT=16 samples x KCHUNK.
// Warp w: m-half (w&1)*8..+8, k-quarter (w>>2) of each KC chunk.
// W staged in smem (coalesced, xor-swizzled); G staged in smem (broadcast reads).
__global__ void __launch_bounds__(256, 2) gemm_kernel(const float* __restrict__ Wt,
                                                      float* __restrict__ out) {
    __shared__ __align__(16) float ws[OT * KC];  // 16 KB
    __shared__ __align__(16) float gs[MT * KC];  // 2 KB

    int tid = threadIdx.x;
    int warp = tid >> 5;
    int lane = tid & 31;

    int s = blockIdx.y >> 2;
    int mtile = (blockIdx.y & 3) * MT;
    int off = g_off[s];
    int count = g_off[s + 1] - off;
    int rows = count - mtile;
    if (rows <= 0) return;
    if (rows > MT) rows = MT;

    int otile = blockIdx.x * OT;
    size_t k0 = (size_t)blockIdx.z * KCHUNK;

    // ---- staging maps ----
    int wrow = tid >> 1;                 // 0..127
    int wcol = (tid & 1) * 16;           // half row (16 floats = 4 float4)
    const float* wgp = Wt + ((size_t)(s * OUT_DIMN + otile + wrow)) * K_VOX + k0 + wcol;
    int wsw = (wrow & 7) << 2;           // store swizzle
    float* wsp = ws + wrow * KC;

    int grow = tid >> 3;                 // 0..31 (only tid<128 used)
    int gcol = (tid & 7) * 4;
    int mglob = mtile + grow;
    int slot = off + (mglob < count ? mglob : count - 1);  // clamp padded rows
    const float* ggp = g_G + (size_t)slot * K_VOX + k0 + gcol;
    float* gdst = &gs[grow * KC + gcol];

    // ---- compute map ----
    int og = lane;                        // output lane; owns og+32r, r=0..3
    int mbase = (warp & 1) * 8;           // 8 m-rows per warp
    int kq = warp >> 1;                   // k-quarter 0..3
    int swW = (og & 7) << 2;              // read swizzle (matches wrow&7 of o-row)

    unsigned long long acc[8][4];
#pragma unroll
    for (int m = 0; m < 8; m++)
#pragma unroll
        for (int r = 0; r < 4; r++) acc[m][r] = 0ULL;

    // register prefetch
    float4 wpre[4];
    float4 gpre;
#pragma unroll
    for (int q = 0; q < 4; q++) wpre[q] = *(const float4*)(wgp + q * 4);
    if (tid < 128) gpre = *(const float4*)ggp;

    for (int it = 0; it < NITER; it++) {
        __syncthreads();
#pragma unroll
        for (int q = 0; q < 4; q++) {
            int cl = wcol + q * 4;
            *(float4*)&wsp[cl ^ wsw] = wpre[q];
        }
        if (tid < 128) *(float4*)gdst = gpre;
        __syncthreads();
        if (it + 1 < NITER) {
            const float* wn = wgp + (size_t)(it + 1) * KC;
#pragma unroll
            for (int q = 0; q < 4; q++) wpre[q] = *(const float4*)(wn + q * 4);
            if (tid < 128) gpre = *(const float4*)(ggp + (size_t)(it + 1) * KC);
        }
        // this warp handles kb = kq*4 and (kq+4)*4 within the 32-float chunk
#pragma unroll
        for (int j = 0; j < 2; j++) {
            int kb = (kq + j * 4) * 4;
            ulonglong2 wv[4];
#pragma unroll
            for (int r = 0; r < 4; r++)
                wv[r] = *(const ulonglong2*)&ws[(og + 32 * r) * KC + (kb ^ swW)];
#pragma unroll
            for (int m = 0; m < 8; m++) {
                ulonglong2 gv = *(const ulonglong2*)&gs[(mbase + m) * KC + kb];  // broadcast
#pragma unroll
                for (int r = 0; r < 4; r++) {
                    acc[m][r] = fma2(gv.x, wv[r].x, acc[m][r]);
                    acc[m][r] = fma2(gv.y, wv[r].y, acc[m][r]);
                }
            }
        }
    }

    // epilogue: fold f32x2 halves, accumulate across k-splits and k-quarters
#pragma unroll
    for (int m = 0; m < 8; m++) {
        int mm = mbase + m;
        if (mm < rows) {
            int b = g_order[off + mtile + mm];
#pragma unroll
            for (int r = 0; r < 4; r++) {
                unsigned long long a = acc[m][r];
                float lo = __uint_as_float((unsigned)(a & 0xffffffffULL));
                float hi = __uint_as_float((unsigned)(a >> 32));
                atomicAdd(&out[b * OUT_DIMN + otile + og + 32 * r], lo + hi);
            }
        }
    }
}

extern "C" void kernel_launch(void* const* d_in, const int* in_sizes, int n_in,
                              void* d_out, int out_size) {
    (void)in_sizes; (void)n_in; (void)out_size;
    const void*  idp  = d_in[0];                 // id_batch (int64 or int32)
    const float* fmri = (const float*)d_in[1];   // [B, D, H, W]
    const int*   idx  = (const int*)d_in[2];     // [S, K]
    const float* Wt   = (const float*)d_in[3];   // [S, OUT, K]
    const float* bias = (const float*)d_in[4];   // [S, OUT]
    float* out = (float*)d_out;                  // [B, 1, OUT]

    setup_kernel<<<1, 32>>>(idp);
    init_out_kernel<<<(B_BATCH * OUT_DIMN + 255) / 256, 256>>>(out, bias);
    gather_kernel<<<dim3((K_VOX + 255) / 256, B_BATCH), 256>>>(fmri, idx);
    gemm_kernel<<<dim3(OUT_DIMN / OT, 16, KSPLIT), 256>>>(Wt, out);
}

// round 4
// speedup vs baseline: 1.5780x; 1.1560x over previous
#include <cuda_runtime.h>
#include <cstdint>

#define S_SUBJ   4
#define B_BATCH  64
#define K_VOX    40000
#define OUT_DIMN 768
#define V_VOX    (64*64*48)

#define OT      64           // outputs per block tile
#define MT      16           // samples per block tile
#define KSPLIT  25           // K split factor
#define KCHUNK  1600         // 40000 / 25
#define KC      64           // smem K chunk (floats)
#define NITER   (KCHUNK/KC)  // 25

// -------- device scratch (allocation-free per harness rules) --------
__device__ float g_G[(size_t)B_BATCH * K_VOX];   // gathered voxels, [slot][k]
__device__ int   g_subj[B_BATCH];                // subject per original sample
__device__ int   g_order[B_BATCH];               // slot -> original sample index
__device__ int   g_slotsubj[B_BATCH];            // slot -> subject
__device__ int   g_off[S_SUBJ + 1];              // subject -> slot range

// -------- 1) grouping + dtype detection --------
__global__ void setup_kernel(const void* idp) {
    if (threadIdx.x != 0) return;
    const int* w = (const int*)idp;
    // int64 detection: ids < 4, so high words are all zero for int64 input.
    bool is64 = true;
    for (int i = 1; i < B_BATCH; i += 2) {
        if (w[i] != 0) { is64 = false; break; }
    }
    int subj[B_BATCH];
    for (int b = 0; b < B_BATCH; b++) {
        int s = is64 ? w[2 * b] : w[b];
        subj[b] = s;
        g_subj[b] = s;
    }
    int cnt[S_SUBJ];
    for (int s = 0; s < S_SUBJ; s++) cnt[s] = 0;
    for (int b = 0; b < B_BATCH; b++) cnt[subj[b]]++;
    int off = 0, pos[S_SUBJ];
    for (int s = 0; s < S_SUBJ; s++) { g_off[s] = off; pos[s] = off; off += cnt[s]; }
    g_off[S_SUBJ] = off;
    for (int b = 0; b < B_BATCH; b++) {
        int s = subj[b];
        int p = pos[s]++;
        g_order[p] = b;
        g_slotsubj[p] = s;
    }
}

// -------- 2) out = bias[subj[b]] --------
__global__ void init_out_kernel(float* out, const float* bias) {
    int i = blockIdx.x * blockDim.x + threadIdx.x;
    if (i >= B_BATCH * OUT_DIMN) return;
    int b = i / OUT_DIMN;
    int o = i - b * OUT_DIMN;
    out[i] = bias[g_subj[b] * OUT_DIMN + o];
}

// -------- 3) gather: G[slot][k] = fmri[order[slot]][idx[subj][k]] --------
__global__ void gather_kernel(const float* __restrict__ fmri, const int* __restrict__ idx) {
    int slot = blockIdx.y;
    int k = blockIdx.x * blockDim.x + threadIdx.x;
    if (k >= K_VOX) return;
    int b = g_order[slot];
    int s = g_slotsubj[slot];
    g_G[(size_t)slot * K_VOX + k] = fmri[(size_t)b * V_VOX + idx[s * K_VOX + k]];
}

// -------- packed fp32x2 FMA (Blackwell-only PTX) --------
__device__ __forceinline__ unsigned long long fma2(unsigned long long a,
                                                   unsigned long long b,
                                                   unsigned long long c) {
    unsigned long long d;
    asm("fma.rn.f32x2 %0, %1, %2, %3;" : "=l"(d) : "l"(a), "l"(b), "l"(c));
    return d;
}

// -------- 4) grouped GEMM: out[b][o] += G[slot] . Wt[s][o] --------
// Block: 256 threads, tile OT=64 outputs x MT=16 samples x KCHUNK.
// Warp w: m-half = (w&1)*8, k-quarter kq = w>>1 (groups kq+4j, j=0..3 of 16).
// W/G staged in smem with line-dense LDG (2 full 256B rows per LDG.128 instr).
// Cross-warp (k-quarter) reduction in smem, then 1 atomicAdd per (m,o) per z.
__global__ void __launch_bounds__(256, 2) gemm_kernel(const float* __restrict__ Wt,
                                                      float* __restrict__ out) {
    __shared__ __align__(16) float ws[OT * KC];  // 16 KB (reused as reduction buf)
    __shared__ __align__(16) float gs[MT * KC];  // 4 KB

    int tid = threadIdx.x;
    int warp = tid >> 5;
    int lane = tid & 31;

    int s = blockIdx.y >> 2;
    int mtile = (blockIdx.y & 3) * MT;
    int off = g_off[s];
    int count = g_off[s + 1] - off;
    int rows = count - mtile;
    if (rows <= 0) return;
    if (rows > MT) rows = MT;

    int otile = blockIdx.x * OT;
    size_t k0 = (size_t)blockIdx.z * KCHUNK;

    // ---- staging maps (line-dense: 16 lanes tile a 256B row, 2 rows/instr) ----
    int wr0  = (tid >> 4) * 4;        // row base for q=0..3  (0,4,...,60)
    int wcol = (tid & 15) * 4;        // 4-float column within row
    const float* wgp = Wt + ((size_t)(s * OUT_DIMN + otile + wr0)) * K_VOX + k0 + wcol;

    int gr = tid >> 4;                // 0..15 : G row (sample)
    int mglob = mtile + gr;
    int slot = off + (mglob < count ? mglob : count - 1);  // clamp padded rows
    const float* ggp = g_G + (size_t)slot * K_VOX + k0 + wcol;
    float* gdst = &gs[gr * KC + wcol];

    // ---- compute map ----
    int og = lane;                    // output lane; owns og, og+32
    int mbase = (warp & 1) * 8;       // 8 m-rows per warp
    int kq = warp >> 1;               // k-quarter 0..3
    int swW = (og & 7) << 2;

    unsigned long long acc[8][2];
#pragma unroll
    for (int m = 0; m < 8; m++) { acc[m][0] = 0ULL; acc[m][1] = 0ULL; }

    // register prefetch
    float4 wpre[4];
    float4 gpre;
#pragma unroll
    for (int q = 0; q < 4; q++) wpre[q] = *(const float4*)(wgp + (size_t)q * K_VOX);
    gpre = *(const float4*)ggp;

    for (int it = 0; it < NITER; it++) {
        __syncthreads();
#pragma unroll
        for (int q = 0; q < 4; q++) {
            int row = wr0 + q;
            *(float4*)&ws[row * KC + (wcol ^ ((row & 7) << 2))] = wpre[q];
        }
        *(float4*)gdst = gpre;
        __syncthreads();
        if (it + 1 < NITER) {
            int nk = (it + 1) * KC;
#pragma unroll
            for (int q = 0; q < 4; q++)
                wpre[q] = *(const float4*)(wgp + (size_t)q * K_VOX + nk);
            gpre = *(const float4*)(ggp + nk);
        }
#pragma unroll
        for (int j = 0; j < 4; j++) {
            int kb = (kq + j * 4) * 4;
            ulonglong2 wv0 = *(const ulonglong2*)&ws[og * KC + (kb ^ swW)];
            ulonglong2 wv1 = *(const ulonglong2*)&ws[(og + 32) * KC + (kb ^ swW)];
#pragma unroll
            for (int m = 0; m < 8; m++) {
                ulonglong2 gv = *(const ulonglong2*)&gs[(mbase + m) * KC + kb]; // bcast
                acc[m][0] = fma2(gv.x, wv0.x, acc[m][0]);
                acc[m][0] = fma2(gv.y, wv0.y, acc[m][0]);
                acc[m][1] = fma2(gv.x, wv1.x, acc[m][1]);
                acc[m][1] = fma2(gv.y, wv1.y, acc[m][1]);
            }
        }
    }

    // ---- cross-warp (kq) reduction in smem, then one atomic per (m,o) ----
    __syncthreads();   // all smem reads of ws/gs done
#pragma unroll
    for (int m = 0; m < 8; m++) {
        int mm = mbase + m;
        unsigned long long a0 = acc[m][0], a1 = acc[m][1];
        float v0 = __uint_as_float((unsigned)(a0 & 0xffffffffULL)) +
                   __uint_as_float((unsigned)(a0 >> 32));
        float v1 = __uint_as_float((unsigned)(a1 & 0xffffffffULL)) +
                   __uint_as_float((unsigned)(a1 >> 32));
        ws[(kq * MT + mm) * OT + og] = v0;
        ws[(kq * MT + mm) * OT + og + 32] = v1;
    }
    __syncthreads();
    int rm = tid >> 4;            // 0..15 : m row
    int rc = (tid & 15) * 4;      // 4 outputs per thread
    if (rm < rows) {
        float4 t0 = *(const float4*)&ws[(0 * MT + rm) * OT + rc];
        float4 t1 = *(const float4*)&ws[(1 * MT + rm) * OT + rc];
        float4 t2 = *(const float4*)&ws[(2 * MT + rm) * OT + rc];
        float4 t3 = *(const float4*)&ws[(3 * MT + rm) * OT + rc];
        int b = g_order[off + mtile + rm];
        float* op = &out[b * OUT_DIMN + otile + rc];
        atomicAdd(op + 0, t0.x + t1.x + t2.x + t3.x);
        atomicAdd(op + 1, t0.y + t1.y + t2.y + t3.y);
        atomicAdd(op + 2, t0.z + t1.z + t2.z + t3.z);
        atomicAdd(op + 3, t0.w + t1.w + t2.w + t3.w);
    }
}

extern "C" void kernel_launch(void* const* d_in, const int* in_sizes, int n_in,
                              void* d_out, int out_size) {
    (void)in_sizes; (void)n_in; (void)out_size;
    const void*  idp  = d_in[0];                 // id_batch (int64 or int32)
    const float* fmri = (const float*)d_in[1];   // [B, D, H, W]
    const int*   idx  = (const int*)d_in[2];     // [S, K]
    const float* Wt   = (const float*)d_in[3];   // [S, OUT, K]
    const float* bias = (const float*)d_in[4];   // [S, OUT]
    float* out = (float*)d_out;                  // [B, 1, OUT]

    setup_kernel<<<1, 32>>>(idp);
    init_out_kernel<<<(B_BATCH * OUT_DIMN + 255) / 256, 256>>>(out, bias);
    gather_kernel<<<dim3((K_VOX + 255) / 256, B_BATCH), 256>>>(fmri, idx);
    gemm_kernel<<<dim3(OUT_DIMN / OT, 16, KSPLIT), 256>>>(Wt, out);
}

// round 5
// speedup vs baseline: 1.8752x; 1.1883x over previous
#include <cuda_runtime.h>
#include <cstdint>

#define S_SUBJ   4
#define B_BATCH  64
#define K_VOX    40000
#define OUT_DIMN 768
#define V_VOX    (64*64*48)

#define OT      128          // outputs per block tile
#define MT      16           // samples per block tile
#define KSPLIT  25           // K split factor
#define KCHUNK  1600         // 40000 / 25
#define KC      64           // smem K chunk (floats)
#define NITER   (KCHUNK/KC)  // 25

#define WS_F    (OT*KC)      // 8192 floats per stage (W)
#define GS_F    (MT*KC)      // 1024 floats per stage (G)
#define STAGE_F (WS_F+GS_F)  // 9216 floats
#define SMEM_BYTES (2*STAGE_F*4)   // 73728 B

// -------- device scratch (allocation-free per harness rules) --------
__device__ float g_G[(size_t)B_BATCH * K_VOX];
__device__ int   g_subj[B_BATCH];
__device__ int   g_order[B_BATCH];
__device__ int   g_slotsubj[B_BATCH];
__device__ int   g_off[S_SUBJ + 1];

// -------- 1) grouping + dtype detection --------
__global__ void setup_kernel(const void* idp) {
    if (threadIdx.x != 0) return;
    const int* w = (const int*)idp;
    bool is64 = true;
    for (int i = 1; i < B_BATCH; i += 2) {
        if (w[i] != 0) { is64 = false; break; }
    }
    int subj[B_BATCH];
    for (int b = 0; b < B_BATCH; b++) {
        int s = is64 ? w[2 * b] : w[b];
        subj[b] = s;
        g_subj[b] = s;
    }
    int cnt[S_SUBJ];
    for (int s = 0; s < S_SUBJ; s++) cnt[s] = 0;
    for (int b = 0; b < B_BATCH; b++) cnt[subj[b]]++;
    int off = 0, pos[S_SUBJ];
    for (int s = 0; s < S_SUBJ; s++) { g_off[s] = off; pos[s] = off; off += cnt[s]; }
    g_off[S_SUBJ] = off;
    for (int b = 0; b < B_BATCH; b++) {
        int s = subj[b];
        int p = pos[s]++;
        g_order[p] = b;
        g_slotsubj[p] = s;
    }
}

// -------- 2) out = bias[subj[b]] --------
__global__ void init_out_kernel(float* out, const float* bias) {
    int i = blockIdx.x * blockDim.x + threadIdx.x;
    if (i >= B_BATCH * OUT_DIMN) return;
    int b = i / OUT_DIMN;
    int o = i - b * OUT_DIMN;
    out[i] = bias[g_subj[b] * OUT_DIMN + o];
}

// -------- 3) gather --------
__global__ void gather_kernel(const float* __restrict__ fmri, const int* __restrict__ idx) {
    int slot = blockIdx.y;
    int k = blockIdx.x * blockDim.x + threadIdx.x;
    if (k >= K_VOX) return;
    int b = g_order[slot];
    int s = g_slotsubj[slot];
    g_G[(size_t)slot * K_VOX + k] = fmri[(size_t)b * V_VOX + idx[s * K_VOX + k]];
}

// -------- asm helpers --------
__device__ __forceinline__ unsigned long long fma2(unsigned long long a,
                                                   unsigned long long b,
                                                   unsigned long long c) {
    unsigned long long d;
    asm("fma.rn.f32x2 %0, %1, %2, %3;" : "=l"(d) : "l"(a), "l"(b), "l"(c));
    return d;
}
__device__ __forceinline__ void cp_async16(void* smem_ptr, const void* gptr) {
    unsigned sa = (unsigned)__cvta_generic_to_shared(smem_ptr);
    asm volatile("cp.async.cg.shared.global [%0], [%1], 16;" :: "r"(sa), "l"(gptr));
}
__device__ __forceinline__ void cp_commit() { asm volatile("cp.async.commit_group;"); }
__device__ __forceinline__ void cp_wait1() { asm volatile("cp.async.wait_group 1;"); }
__device__ __forceinline__ void cp_wait0() { asm volatile("cp.async.wait_group 0;"); }

// -------- 4) grouped GEMM: out[b][o] += G[slot] . Wt[s][o] --------
// OT=128 x MT=16 x KCHUNK per block. Warp = (m-half)(w&1) x (k-quarter)(w>>1).
// cp.async 2-stage pipeline; acc[8][4] f32x2; smem kq-reduction then atomics.
__global__ void __launch_bounds__(256, 2) gemm_kernel(const float* __restrict__ Wt,
                                                      float* __restrict__ out) {
    extern __shared__ float smem[];

    int tid = threadIdx.x;
    int warp = tid >> 5;
    int lane = tid & 31;

    int s = blockIdx.y >> 2;
    int mtile = (blockIdx.y & 3) * MT;
    int off = g_off[s];
    int count = g_off[s + 1] - off;
    int rows = count - mtile;
    if (rows <= 0) return;
    if (rows > MT) rows = MT;

    int otile = blockIdx.x * OT;
    size_t k0 = (size_t)blockIdx.z * KCHUNK;

    // ---- staging maps: thread -> 8 W cells (rows rbase+16q) + 1 G cell ----
    int cell = tid & 15;            // 16B cell within 64-float row
    int rbase = tid >> 4;           // 0..15
    int rsw = rbase & 7;            // row swizzle key (invariant over q)
    const float* wbase = Wt + ((size_t)(s * OUT_DIMN + otile)) * K_VOX + k0;
    int mglob = mtile + rbase;
    int slot = off + (mglob < count ? mglob : count - 1);
    const float* gbase = g_G + (size_t)slot * K_VOX + k0 + cell * 4;

    // ---- compute map ----
    int og = lane;
    int mbase = (warp & 1) * 8;
    int kq = warp >> 1;
    int swo = og & 7;

    unsigned long long acc[8][4];
#pragma unroll
    for (int m = 0; m < 8; m++)
#pragma unroll
        for (int r = 0; r < 4; r++) acc[m][r] = 0ULL;

#define ISSUE(IT, ST)                                                          \
    do {                                                                       \
        float* wsb = smem + (ST) * STAGE_F;                                    \
        float* gsb = wsb + WS_F;                                               \
        const float* wsrc = wbase + (IT) * KC + cell * 4;                      \
        _Pragma("unroll")                                                      \
        for (int q = 0; q < 8; q++) {                                          \
            int row = rbase + 16 * q;                                          \
            cp_async16(&wsb[row * KC + 4 * (cell ^ rsw)],                      \
                       wsrc + (size_t)row * K_VOX);                            \
        }                                                                      \
        cp_async16(&gsb[rbase * KC + cell * 4], gbase + (IT) * KC);            \
        cp_commit();                                                           \
    } while (0)

    ISSUE(0, 0);

    for (int it = 0; it < NITER; it++) {
        int st = it & 1;
        if (it + 1 < NITER) { ISSUE(it + 1, st ^ 1); cp_wait1(); }
        else                { cp_wait0(); }
        __syncthreads();

        const float* ws = smem + st * STAGE_F;
        const float* gs = ws + WS_F;
#pragma unroll
        for (int j = 0; j < 4; j++) {
            int cellk = kq + 4 * j;
            int kb = cellk * 4;
            ulonglong2 wv[4];
#pragma unroll
            for (int r = 0; r < 4; r++)
                wv[r] = *(const ulonglong2*)&ws[(og + 32 * r) * KC + 4 * (cellk ^ swo)];
#pragma unroll
            for (int m = 0; m < 8; m++) {
                ulonglong2 gv = *(const ulonglong2*)&gs[(mbase + m) * KC + kb];
#pragma unroll
                for (int r = 0; r < 4; r++) {
                    acc[m][r] = fma2(gv.x, wv[r].x, acc[m][r]);
                    acc[m][r] = fma2(gv.y, wv[r].y, acc[m][r]);
                }
            }
        }
        __syncthreads();
    }
#undef ISSUE

    // ---- kq reduction in smem (reuse stage buffers), then atomics ----
    float* red = smem;   // 4*16*128 = 8192 floats
#pragma unroll
    for (int m = 0; m < 8; m++) {
        int mm = mbase + m;
#pragma unroll
        for (int r = 0; r < 4; r++) {
            unsigned long long a = acc[m][r];
            float v = __uint_as_float((unsigned)(a & 0xffffffffULL)) +
                      __uint_as_float((unsigned)(a >> 32));
            red[((kq * MT + mm) << 7) + og + 32 * r] = v;
        }
    }
    __syncthreads();
    int rm = tid >> 4;
    int oc = (tid & 15) * 8;
    if (rm < rows) {
        float sum[8];
#pragma unroll
        for (int i = 0; i < 8; i++) sum[i] = 0.f;
#pragma unroll
        for (int q = 0; q < 4; q++) {
            const float* rp = &red[((q * MT + rm) << 7) + oc];
            float4 a = *(const float4*)rp;
            float4 b = *(const float4*)(rp + 4);
            sum[0] += a.x; sum[1] += a.y; sum[2] += a.z; sum[3] += a.w;
            sum[4] += b.x; sum[5] += b.y; sum[6] += b.z; sum[7] += b.w;
        }
        int b = g_order[off + mtile + rm];
        float* op = &out[b * OUT_DIMN + otile + oc];
#pragma unroll
        for (int i = 0; i < 8; i++) atomicAdd(op + i, sum[i]);
    }
}

extern "C" void kernel_launch(void* const* d_in, const int* in_sizes, int n_in,
                              void* d_out, int out_size) {
    (void)in_sizes; (void)n_in; (void)out_size;
    const void*  idp  = d_in[0];
    const float* fmri = (const float*)d_in[1];
    const int*   idx  = (const int*)d_in[2];
    const float* Wt   = (const float*)d_in[3];
    const float* bias = (const float*)d_in[4];
    float* out = (float*)d_out;

    static bool attr_set = false;
    if (!attr_set) {
        cudaFuncSetAttribute(gemm_kernel,
                             cudaFuncAttributeMaxDynamicSharedMemorySize, SMEM_BYTES);
        attr_set = true;
    }

    setup_kernel<<<1, 32>>>(idp);
    init_out_kernel<<<(B_BATCH * OUT_DIMN + 255) / 256, 256>>>(out, bias);
    gather_kernel<<<dim3((K_VOX + 255) / 256, B_BATCH), 256>>>(fmri, idx);
    gemm_kernel<<<dim3(OUT_DIMN / OT, 16, KSPLIT), 256, SMEM_BYTES>>>(Wt, out);
}

// round 6
// speedup vs baseline: 2.0430x; 1.0895x over previous
#include <cuda_runtime.h>
#include <cstdint>

#define S_SUBJ   4
#define B_BATCH  64
#define K_VOX    40000
#define OUT_DIMN 768
#define V_VOX    (64*64*48)

#define OT      128          // outputs per block tile
#define MT      16           // samples per block tile
#define KSPLIT  25           // K split factor
#define KCHUNK  1600         // 40000 / 25
#define KC      64           // smem K chunk (floats)
#define NITER   (KCHUNK/KC)  // 25
#define STAGES  3

#define WS_F    (OT*KC)      // 8192 floats per stage (W)
#define GS_F    (MT*KC)      // 1024 floats per stage (G)
#define STAGE_F (WS_F+GS_F)  // 9216 floats
#define SMEM_BYTES (STAGES*STAGE_F*4)   // 110592 B

// -------- device scratch (allocation-free per harness rules) --------
__device__ float g_G[(size_t)B_BATCH * K_VOX];
__device__ int   g_subj[B_BATCH];
__device__ int   g_order[B_BATCH];
__device__ int   g_slotsubj[B_BATCH];
__device__ int   g_off[S_SUBJ + 1];

// -------- 1) grouping + dtype detection --------
__global__ void setup_kernel(const void* idp) {
    if (threadIdx.x != 0) return;
    const int* w = (const int*)idp;
    bool is64 = true;
    for (int i = 1; i < B_BATCH; i += 2) {
        if (w[i] != 0) { is64 = false; break; }
    }
    int subj[B_BATCH];
    for (int b = 0; b < B_BATCH; b++) {
        int s = is64 ? w[2 * b] : w[b];
        subj[b] = s;
        g_subj[b] = s;
    }
    int cnt[S_SUBJ];
    for (int s = 0; s < S_SUBJ; s++) cnt[s] = 0;
    for (int b = 0; b < B_BATCH; b++) cnt[subj[b]]++;
    int off = 0, pos[S_SUBJ];
    for (int s = 0; s < S_SUBJ; s++) { g_off[s] = off; pos[s] = off; off += cnt[s]; }
    g_off[S_SUBJ] = off;
    for (int b = 0; b < B_BATCH; b++) {
        int s = subj[b];
        int p = pos[s]++;
        g_order[p] = b;
        g_slotsubj[p] = s;
    }
}

// -------- 2) out = bias[subj[b]] --------
__global__ void init_out_kernel(float* out, const float* bias) {
    int i = blockIdx.x * blockDim.x + threadIdx.x;
    if (i >= B_BATCH * OUT_DIMN) return;
    int b = i / OUT_DIMN;
    int o = i - b * OUT_DIMN;
    out[i] = bias[g_subj[b] * OUT_DIMN + o];
}

// -------- 3) gather --------
__global__ void gather_kernel(const float* __restrict__ fmri, const int* __restrict__ idx) {
    int slot = blockIdx.y;
    int k = blockIdx.x * blockDim.x + threadIdx.x;
    if (k >= K_VOX) return;
    int b = g_order[slot];
    int s = g_slotsubj[slot];
    g_G[(size_t)slot * K_VOX + k] = fmri[(size_t)b * V_VOX + idx[s * K_VOX + k]];
}

// -------- asm helpers --------
__device__ __forceinline__ unsigned long long fma2(unsigned long long a,
                                                   unsigned long long b,
                                                   unsigned long long c) {
    unsigned long long d;
    asm("fma.rn.f32x2 %0, %1, %2, %3;" : "=l"(d) : "l"(a), "l"(b), "l"(c));
    return d;
}
__device__ __forceinline__ void cp_async16(void* smem_ptr, const void* gptr) {
    unsigned sa = (unsigned)__cvta_generic_to_shared(smem_ptr);
    asm volatile("cp.async.cg.shared.global [%0], [%1], 16;" :: "r"(sa), "l"(gptr));
}
__device__ __forceinline__ void cp_commit() { asm volatile("cp.async.commit_group;"); }
__device__ __forceinline__ void cp_wait1() { asm volatile("cp.async.wait_group 1;"); }
__device__ __forceinline__ void cp_wait0() { asm volatile("cp.async.wait_group 0;"); }

// -------- 4) grouped GEMM: out[b][o] += G[slot] . Wt[s][o] --------
// OT=128 x MT=16 x KCHUNK. 3-stage cp.async pipeline, ONE barrier per chunk:
//   wait(group it) -> barrier -> issue(it+2) -> compute(it)
// Stage read at it-1 is only overwritten by issue(it+2) placed after the
// barrier that all warps reach only after finishing compute(it-1).
__global__ void __launch_bounds__(256, 2) gemm_kernel(const float* __restrict__ Wt,
                                                      float* __restrict__ out) {
    extern __shared__ float smem[];

    int tid = threadIdx.x;
    int warp = tid >> 5;
    int lane = tid & 31;

    int s = blockIdx.y >> 2;
    int mtile = (blockIdx.y & 3) * MT;
    int off = g_off[s];
    int count = g_off[s + 1] - off;
    int rows = count - mtile;
    if (rows <= 0) return;
    if (rows > MT) rows = MT;

    int otile = blockIdx.x * OT;
    size_t k0 = (size_t)blockIdx.z * KCHUNK;

    // ---- staging maps: thread -> 8 W cells (rows rbase+16q) + 1 G cell ----
    int cell = tid & 15;            // 16B cell within 64-float row
    int rbase = tid >> 4;           // 0..15
    int rsw = rbase & 7;
    const float* wbase = Wt + ((size_t)(s * OUT_DIMN + otile)) * K_VOX + k0;
    int mglob = mtile + rbase;
    int slot = off + (mglob < count ? mglob : count - 1);
    const float* gbase = g_G + (size_t)slot * K_VOX + k0 + cell * 4;

    // ---- compute map ----
    int og = lane;
    int mbase = (warp & 1) * 8;
    int kq = warp >> 1;
    int swo = og & 7;
    // hoisted swizzled k-cell offsets for the 4 j-groups (loop-invariant)
    int woff[4], koff[4];
#pragma unroll
    for (int j = 0; j < 4; j++) {
        int cellk = kq + 4 * j;
        woff[j] = 4 * (cellk ^ swo);
        koff[j] = 4 * cellk;
    }

    unsigned long long acc[8][4];
#pragma unroll
    for (int m = 0; m < 8; m++)
#pragma unroll
        for (int r = 0; r < 4; r++) acc[m][r] = 0ULL;

#define ISSUE(IT, WSB)                                                         \
    do {                                                                       \
        float* wsb_ = (WSB);                                                   \
        float* gsb_ = wsb_ + WS_F;                                             \
        const float* wsrc = wbase + (IT) * KC + cell * 4;                      \
        _Pragma("unroll")                                                      \
        for (int q = 0; q < 8; q++) {                                          \
            int row = rbase + 16 * q;                                          \
            cp_async16(&wsb_[row * KC + 4 * (cell ^ rsw)],                     \
                       wsrc + (size_t)row * K_VOX);                            \
        }                                                                      \
        cp_async16(&gsb_[rbase * KC + cell * 4], gbase + (IT) * KC);           \
        cp_commit();                                                           \
    } while (0)

    float* const smem_end = smem + STAGES * STAGE_F;
    ISSUE(0, smem);
    ISSUE(1, smem + STAGE_F);

    float* rd = smem;                      // stage being computed (it % 3)
    float* wr = smem + 2 * STAGE_F;        // stage to issue into ((it+2) % 3)

    for (int it = 0; it < NITER; it++) {
        if (it + 1 < NITER) cp_wait1(); else cp_wait0();
        __syncthreads();
        if (it + 2 < NITER) {
            ISSUE(it + 2, wr);
            wr += STAGE_F; if (wr == smem_end) wr = smem;
        }

        const float* ws = rd;
        const float* gs = rd + WS_F;
        rd += STAGE_F; if (rd == smem_end) rd = smem;

#pragma unroll
        for (int j = 0; j < 4; j++) {
            ulonglong2 wv[4];
#pragma unroll
            for (int r = 0; r < 4; r++)
                wv[r] = *(const ulonglong2*)&ws[(og + 32 * r) * KC + woff[j]];
#pragma unroll
            for (int m = 0; m < 8; m++) {
                ulonglong2 gv = *(const ulonglong2*)&gs[(mbase + m) * KC + koff[j]];
#pragma unroll
                for (int r = 0; r < 4; r++) {
                    acc[m][r] = fma2(gv.x, wv[r].x, acc[m][r]);
                    acc[m][r] = fma2(gv.y, wv[r].y, acc[m][r]);
                }
            }
        }
    }
#undef ISSUE

    // ---- kq reduction in smem, then atomics ----
    __syncthreads();
    float* red = smem;   // 4*16*128 = 8192 floats
#pragma unroll
    for (int m = 0; m < 8; m++) {
        int mm = mbase + m;
#pragma unroll
        for (int r = 0; r < 4; r++) {
            unsigned long long a = acc[m][r];
            float v = __uint_as_float((unsigned)(a & 0xffffffffULL)) +
                      __uint_as_float((unsigned)(a >> 32));
            red[((kq * MT + mm) << 7) + og + 32 * r] = v;
        }
    }
    __syncthreads();
    int rm = tid >> 4;
    int oc = (tid & 15) * 8;
    if (rm < rows) {
        float sum[8];
#pragma unroll
        for (int i = 0; i < 8; i++) sum[i] = 0.f;
#pragma unroll
        for (int q = 0; q < 4; q++) {
            const float* rp = &red[((q * MT + rm) << 7) + oc];
            float4 a = *(const float4*)rp;
            float4 b = *(const float4*)(rp + 4);
            sum[0] += a.x; sum[1] += a.y; sum[2] += a.z; sum[3] += a.w;
            sum[4] += b.x; sum[5] += b.y; sum[6] += b.z; sum[7] += b.w;
        }
        int b = g_order[off + mtile + rm];
        float* op = &out[b * OUT_DIMN + otile + oc];
#pragma unroll
        for (int i = 0; i < 8; i++) atomicAdd(op + i, sum[i]);
    }
}

extern "C" void kernel_launch(void* const* d_in, const int* in_sizes, int n_in,
                              void* d_out, int out_size) {
    (void)in_sizes; (void)n_in; (void)out_size;
    const void*  idp  = d_in[0];
    const float* fmri = (const float*)d_in[1];
    const int*   idx  = (const int*)d_in[2];
    const float* Wt   = (const float*)d_in[3];
    const float* bias = (const float*)d_in[4];
    float* out = (float*)d_out;

    static bool attr_set = false;
    if (!attr_set) {
        cudaFuncSetAttribute(gemm_kernel,
                             cudaFuncAttributeMaxDynamicSharedMemorySize, SMEM_BYTES);
        attr_set = true;
    }

    setup_kernel<<<1, 32>>>(idp);
    init_out_kernel<<<(B_BATCH * OUT_DIMN + 255) / 256, 256>>>(out, bias);
    gather_kernel<<<dim3((K_VOX + 255) / 256, B_BATCH), 256>>>(fmri, idx);
    gemm_kernel<<<dim3(OUT_DIMN / OT, 16, KSPLIT), 256, SMEM_BYTES>>>(Wt, out);
}

// round 7
// speedup vs baseline: 2.0567x; 1.0067x over previous
#include <cuda_runtime.h>
#include <cstdint>

#define S_SUBJ   4
#define B_BATCH  64
#define K_VOX    40000
#define OUT_DIMN 768
#define V_VOX    (64*64*48)

#define OT      128          // outputs per block tile
#define MT      16           // samples per block tile
#define KSPLIT  25           // K split factor
#define KCHUNK  1600         // 40000 / 25
#define KC      64           // smem K chunk (floats)
#define NITER   (KCHUNK/KC)  // 25
#define STAGES  3

#define WS_F    (OT*KC)      // 8192 floats per stage (W)
#define GS_F    (MT*KC)      // 1024 floats per stage (G)
#define STAGE_F (WS_F+GS_F)  // 9216 floats
#define SMEM_BYTES (STAGES*STAGE_F*4)   // 110592 B

// -------- device scratch (allocation-free per harness rules) --------
__device__ float g_G[(size_t)B_BATCH * K_VOX];
__device__ int   g_subj[B_BATCH];
__device__ int   g_order[B_BATCH];
__device__ int   g_slotsubj[B_BATCH];
__device__ int   g_off[S_SUBJ + 1];

// -------- 1) grouping + dtype detection --------
__global__ void setup_kernel(const void* idp) {
    if (threadIdx.x != 0) return;
    const int* w = (const int*)idp;
    bool is64 = true;
    for (int i = 1; i < B_BATCH; i += 2) {
        if (w[i] != 0) { is64 = false; break; }
    }
    int subj[B_BATCH];
    for (int b = 0; b < B_BATCH; b++) {
        int s = is64 ? w[2 * b] : w[b];
        subj[b] = s;
        g_subj[b] = s;
    }
    int cnt[S_SUBJ];
    for (int s = 0; s < S_SUBJ; s++) cnt[s] = 0;
    for (int b = 0; b < B_BATCH; b++) cnt[subj[b]]++;
    int off = 0, pos[S_SUBJ];
    for (int s = 0; s < S_SUBJ; s++) { g_off[s] = off; pos[s] = off; off += cnt[s]; }
    g_off[S_SUBJ] = off;
    for (int b = 0; b < B_BATCH; b++) {
        int s = subj[b];
        int p = pos[s]++;
        g_order[p] = b;
        g_slotsubj[p] = s;
    }
}

// -------- 2) out = bias[subj[b]] --------
__global__ void init_out_kernel(float* out, const float* bias) {
    int i = blockIdx.x * blockDim.x + threadIdx.x;
    if (i >= B_BATCH * OUT_DIMN) return;
    int b = i / OUT_DIMN;
    int o = i - b * OUT_DIMN;
    out[i] = bias[g_subj[b] * OUT_DIMN + o];
}

// -------- 3) gather --------
__global__ void gather_kernel(const float* __restrict__ fmri, const int* __restrict__ idx) {
    int slot = blockIdx.y;
    int k = blockIdx.x * blockDim.x + threadIdx.x;
    if (k >= K_VOX) return;
    int b = g_order[slot];
    int s = g_slotsubj[slot];
    g_G[(size_t)slot * K_VOX + k] = fmri[(size_t)b * V_VOX + idx[s * K_VOX + k]];
}

// -------- asm helpers --------
__device__ __forceinline__ void fma2acc(unsigned long long& d,
                                        unsigned long long a,
                                        unsigned long long b) {
    asm("fma.rn.f32x2 %0, %1, %2, %0;" : "+l"(d) : "l"(a), "l"(b));
}
__device__ __forceinline__ void cp_async16(void* smem_ptr, const void* gptr) {
    unsigned sa = (unsigned)__cvta_generic_to_shared(smem_ptr);
    asm volatile("cp.async.cg.shared.global [%0], [%1], 16;" :: "r"(sa), "l"(gptr));
}
__device__ __forceinline__ void cp_commit() { asm volatile("cp.async.commit_group;"); }
__device__ __forceinline__ void cp_wait1() { asm volatile("cp.async.wait_group 1;"); }
__device__ __forceinline__ void cp_wait0() { asm volatile("cp.async.wait_group 0;"); }

// -------- 4) grouped GEMM: out[b][o] += G[slot] . Wt[s][o] --------
// OT=128 x MT=16 x KCHUNK. 3-stage cp.async pipeline, one barrier per chunk.
// Inner loop: wv double-buffered across the 4 j-groups; in-place f32x2 FMA.
__global__ void __launch_bounds__(256, 2) gemm_kernel(const float* __restrict__ Wt,
                                                      float* __restrict__ out) {
    extern __shared__ float smem[];

    int tid = threadIdx.x;
    int warp = tid >> 5;
    int lane = tid & 31;

    int s = blockIdx.y >> 2;
    int mtile = (blockIdx.y & 3) * MT;
    int off = g_off[s];
    int count = g_off[s + 1] - off;
    int rows = count - mtile;
    if (rows <= 0) return;
    if (rows > MT) rows = MT;

    int otile = blockIdx.x * OT;
    size_t k0 = (size_t)blockIdx.z * KCHUNK;

    // ---- staging maps ----
    int cell = tid & 15;
    int rbase = tid >> 4;
    int rsw = rbase & 7;
    const float* wbase = Wt + ((size_t)(s * OUT_DIMN + otile)) * K_VOX + k0;
    int mglob = mtile + rbase;
    int slot = off + (mglob < count ? mglob : count - 1);
    const float* gbase = g_G + (size_t)slot * K_VOX + k0 + cell * 4;

    // ---- compute map ----
    int og = lane;
    int mbase = (warp & 1) * 8;
    int kq = warp >> 1;
    int swo = og & 7;
    int woff[4], koff[4];
#pragma unroll
    for (int j = 0; j < 4; j++) {
        int cellk = kq + 4 * j;
        woff[j] = 4 * (cellk ^ swo);
        koff[j] = 4 * cellk;
    }

    unsigned long long acc[8][4];
#pragma unroll
    for (int m = 0; m < 8; m++)
#pragma unroll
        for (int r = 0; r < 4; r++) acc[m][r] = 0ULL;

#define ISSUE(IT, WSB)                                                         \
    do {                                                                       \
        float* wsb_ = (WSB);                                                   \
        float* gsb_ = wsb_ + WS_F;                                             \
        const float* wsrc = wbase + (IT) * KC + cell * 4;                      \
        _Pragma("unroll")                                                      \
        for (int q = 0; q < 8; q++) {                                          \
            int row = rbase + 16 * q;                                          \
            cp_async16(&wsb_[row * KC + 4 * (cell ^ rsw)],                     \
                       wsrc + (size_t)row * K_VOX);                            \
        }                                                                      \
        cp_async16(&gsb_[rbase * KC + cell * 4], gbase + (IT) * KC);           \
        cp_commit();                                                           \
    } while (0)

    float* const smem_end = smem + STAGES * STAGE_F;
    ISSUE(0, smem);
    ISSUE(1, smem + STAGE_F);

    float* rd = smem;
    float* wr = smem + 2 * STAGE_F;

    for (int it = 0; it < NITER; it++) {
        if (it + 1 < NITER) cp_wait1(); else cp_wait0();
        __syncthreads();
        if (it + 2 < NITER) {
            ISSUE(it + 2, wr);
            wr += STAGE_F; if (wr == smem_end) wr = smem;
        }

        const float* wsp = rd + og * KC;          // per-thread W base
        const float* gsp = rd + WS_F + mbase * KC; // per-warp G base
        rd += STAGE_F; if (rd == smem_end) rd = smem;

        ulonglong2 wvA[4], wvB[4];
#pragma unroll
        for (int r = 0; r < 4; r++)
            wvA[r] = *(const ulonglong2*)&wsp[r * 32 * KC + woff[0]];

#define COMPUTE_J(WV, J)                                                       \
    do {                                                                       \
        _Pragma("unroll")                                                      \
        for (int m = 0; m < 8; m++) {                                          \
            ulonglong2 gv = *(const ulonglong2*)&gsp[m * KC + koff[J]];        \
            _Pragma("unroll")                                                  \
            for (int r = 0; r < 4; r++) {                                      \
                fma2acc(acc[m][r], gv.x, (WV)[r].x);                           \
                fma2acc(acc[m][r], gv.y, (WV)[r].y);                           \
            }                                                                  \
        }                                                                      \
    } while (0)

#pragma unroll
        for (int r = 0; r < 4; r++)
            wvB[r] = *(const ulonglong2*)&wsp[r * 32 * KC + woff[1]];
        COMPUTE_J(wvA, 0);
#pragma unroll
        for (int r = 0; r < 4; r++)
            wvA[r] = *(const ulonglong2*)&wsp[r * 32 * KC + woff[2]];
        COMPUTE_J(wvB, 1);
#pragma unroll
        for (int r = 0; r < 4; r++)
            wvB[r] = *(const ulonglong2*)&wsp[r * 32 * KC + woff[3]];
        COMPUTE_J(wvA, 2);
        COMPUTE_J(wvB, 3);
#undef COMPUTE_J
    }
#undef ISSUE

    // ---- kq reduction in smem, then atomics ----
    __syncthreads();
    float* red = smem;
#pragma unroll
    for (int m = 0; m < 8; m++) {
        int mm = mbase + m;
#pragma unroll
        for (int r = 0; r < 4; r++) {
            unsigned long long a = acc[m][r];
            float v = __uint_as_float((unsigned)(a & 0xffffffffULL)) +
                      __uint_as_float((unsigned)(a >> 32));
            red[((kq * MT + mm) << 7) + og + 32 * r] = v;
        }
    }
    __syncthreads();
    int rm = tid >> 4;
    int oc = (tid & 15) * 8;
    if (rm < rows) {
        float sum[8];
#pragma unroll
        for (int i = 0; i < 8; i++) sum[i] = 0.f;
#pragma unroll
        for (int q = 0; q < 4; q++) {
            const float* rp = &red[((q * MT + rm) << 7) + oc];
            float4 a = *(const float4*)rp;
            float4 b = *(const float4*)(rp + 4);
            sum[0] += a.x; sum[1] += a.y; sum[2] += a.z; sum[3] += a.w;
            sum[4] += b.x; sum[5] += b.y; sum[6] += b.z; sum[7] += b.w;
        }
        int b = g_order[off + mtile + rm];
        float* op = &out[b * OUT_DIMN + otile + oc];
#pragma unroll
        for (int i = 0; i < 8; i++) atomicAdd(op + i, sum[i]);
    }
}

extern "C" void kernel_launch(void* const* d_in, const int* in_sizes, int n_in,
                              void* d_out, int out_size) {
    (void)in_sizes; (void)n_in; (void)out_size;
    const void*  idp  = d_in[0];
    const float* fmri = (const float*)d_in[1];
    const int*   idx  = (const int*)d_in[2];
    const float* Wt   = (const float*)d_in[3];
    const float* bias = (const float*)d_in[4];
    float* out = (float*)d_out;

    static bool attr_set = false;
    if (!attr_set) {
        cudaFuncSetAttribute(gemm_kernel,
                             cudaFuncAttributeMaxDynamicSharedMemorySize, SMEM_BYTES);
        attr_set = true;
    }

    setup_kernel<<<1, 32>>>(idp);
    init_out_kernel<<<(B_BATCH * OUT_DIMN + 255) / 256, 256>>>(out, bias);
    gather_kernel<<<dim3((K_VOX + 255) / 256, B_BATCH), 256>>>(fmri, idx);
    gemm_kernel<<<dim3(OUT_DIMN / OT, 16, KSPLIT), 256, SMEM_BYTES>>>(Wt, out);
}

// round 10
// speedup vs baseline: 2.3594x; 1.1472x over previous
#include <cuda_runtime.h>
#include <cstdint>

#define S_SUBJ   4
#define B_BATCH  64
#define K_VOX    40000
#define OUT_DIMN 768
#define V_VOX    (64*64*48)

#define OT      128          // outputs per block tile
#define MT      16           // samples per block tile (= MMA M)
#define KSPLIT  25
#define KCHUNK  1600
#define KC      64           // K per smem chunk
#define NITER   (KCHUNK/KC)  // 25
#define STAGES  3

#define WSTRIDE 68           // padded row stride (floats) -> conflict-free LDS.32
#define WS_F    (OT*WSTRIDE) // 8704 floats
#define GS_F    (MT*WSTRIDE) // 1088 floats
#define STAGE_F (WS_F+GS_F)  // 9792 floats
#define STAGE_B (STAGE_F*4)  // 39168 B
#define SMEM_BYTES (STAGES*STAGE_B)   // 117504 B

// -------- device scratch (allocation-free per harness rules) --------
__device__ float g_G[(size_t)B_BATCH * K_VOX];
__device__ int   g_subj[B_BATCH];
__device__ int   g_order[B_BATCH];
__device__ int   g_slotsubj[B_BATCH];
__device__ int   g_off[S_SUBJ + 1];

// -------- 1) grouping + dtype detection --------
__global__ void setup_kernel(const void* idp) {
    if (threadIdx.x != 0) return;
    const int* w = (const int*)idp;
    bool is64 = true;
    for (int i = 1; i < B_BATCH; i += 2) {
        if (w[i] != 0) { is64 = false; break; }
    }
    int subj[B_BATCH];
    for (int b = 0; b < B_BATCH; b++) {
        int s = is64 ? w[2 * b] : w[b];
        subj[b] = s;
        g_subj[b] = s;
    }
    int cnt[S_SUBJ];
    for (int s = 0; s < S_SUBJ; s++) cnt[s] = 0;
    for (int b = 0; b < B_BATCH; b++) cnt[subj[b]]++;
    int off = 0, pos[S_SUBJ];
    for (int s = 0; s < S_SUBJ; s++) { g_off[s] = off; pos[s] = off; off += cnt[s]; }
    g_off[S_SUBJ] = off;
    for (int b = 0; b < B_BATCH; b++) {
        int s = subj[b];
        int p = pos[s]++;
        g_order[p] = b;
        g_slotsubj[p] = s;
    }
}

// -------- 2) out = bias[subj[b]] --------
__global__ void init_out_kernel(float* out, const float* bias) {
    int i = blockIdx.x * blockDim.x + threadIdx.x;
    if (i >= B_BATCH * OUT_DIMN) return;
    int b = i / OUT_DIMN;
    int o = i - b * OUT_DIMN;
    out[i] = bias[g_subj[b] * OUT_DIMN + o];
}

// -------- 3) gather (pre-rounds G to tf32-RNA: A-side MMA truncation exact) ----
__global__ void gather_kernel(const float* __restrict__ fmri, const int* __restrict__ idx) {
    int slot = blockIdx.y;
    int k = blockIdx.x * blockDim.x + threadIdx.x;
    if (k >= K_VOX) return;
    int b = g_order[slot];
    int s = g_slotsubj[slot];
    float v = fmri[(size_t)b * V_VOX + idx[s * K_VOX + k]];
    uint32_t bits;
    asm("cvt.rna.tf32.f32 %0, %1;" : "=r"(bits) : "f"(v));
    g_G[(size_t)slot * K_VOX + k] = __uint_as_float(bits);
}

// -------- asm helpers --------
__device__ __forceinline__ void cp_async16(uint32_t smem_addr, const void* gptr) {
    asm volatile("cp.async.cg.shared.global [%0], [%1], 16;" :: "r"(smem_addr), "l"(gptr));
}
__device__ __forceinline__ void cp_commit() { asm volatile("cp.async.commit_group;"); }
__device__ __forceinline__ void cp_wait1() { asm volatile("cp.async.wait_group 1;"); }
__device__ __forceinline__ void cp_wait0() { asm volatile("cp.async.wait_group 0;"); }
__device__ __forceinline__ uint32_t tf32_rna(float f) {
    uint32_t r;
    asm("cvt.rna.tf32.f32 %0, %1;" : "=r"(r) : "f"(f));
    return r;
}
__device__ __forceinline__ void mma_tf32(float* c, uint32_t a0, uint32_t a1,
                                         uint32_t a2, uint32_t a3,
                                         uint32_t b0, uint32_t b1) {
    asm volatile(
        "mma.sync.aligned.m16n8k8.row.col.f32.tf32.tf32.f32 "
        "{%0,%1,%2,%3}, {%4,%5,%6,%7}, {%8,%9}, {%0,%1,%2,%3};"
        : "+f"(c[0]), "+f"(c[1]), "+f"(c[2]), "+f"(c[3])
        : "r"(a0), "r"(a1), "r"(a2), "r"(a3), "r"(b0), "r"(b1));
}

// -------- 4) grouped GEMM via mma.sync tf32 (HMMA) --------
// OT=128 x MT=16 x KCHUNK. Warp w: o-half (w&1)*64, k-quarter kq=w>>1
// (k-steps kq, kq+4 of 8 per chunk). 3-stage cp.async pipeline.
__global__ void __launch_bounds__(256, 1) gemm_kernel(const float* __restrict__ Wt,
                                                      float* __restrict__ out) {
    extern __shared__ __align__(16) float smem[];

    int tid = threadIdx.x;
    int warp = tid >> 5;
    int lane = tid & 31;

    int s = blockIdx.y >> 2;
    int mtile = (blockIdx.y & 3) * MT;
    int off = g_off[s];
    int count = g_off[s + 1] - off;
    int rows = count - mtile;
    if (rows <= 0) return;
    if (rows > MT) rows = MT;

    int otile = blockIdx.x * OT;
    size_t k0 = (size_t)blockIdx.z * KCHUNK;

    uint32_t smem_b;
    asm("{ .reg .u64 t; cvta.to.shared.u64 t, %1; cvt.u32.u64 %0, t; }"
        : "=r"(smem_b) : "l"(smem));

    // ---- staging map: thread -> cell (t&15), row base (t>>4) ----
    int cell = tid & 15;
    int rb = tid >> 4;                  // 0..15
    const float* wbase = Wt + (size_t)(s * OUT_DIMN + otile + rb) * K_VOX + k0 + cell * 4;
    int mglob = mtile + rb;
    int slot = off + (mglob < count ? mglob : count - 1);
    const float* gbase = g_G + (size_t)slot * K_VOX + k0 + cell * 4;
    uint32_t wdoff = rb * (WSTRIDE * 4) + cell * 16;          // smem dst offset

    // ---- compute map ----
    int ohalf = (warp & 1) * 64;
    int kq = warp >> 1;                 // 0..3
    int lg = lane >> 2;                 // group id 0..7
    int lt = lane & 3;                  // thread-in-group

    float acc[8][4];
#pragma unroll
    for (int j = 0; j < 8; j++)
#pragma unroll
        for (int r = 0; r < 4; r++) acc[j][r] = 0.f;

#define ISSUE(IT, ST)                                                          \
    do {                                                                       \
        uint32_t wsb = smem_b + (ST) * STAGE_B;                                \
        const float* wsrc = wbase + (IT) * KC;                                 \
        _Pragma("unroll")                                                      \
        for (int q = 0; q < 8; q++)                                            \
            cp_async16(wsb + wdoff + q * (16 * WSTRIDE * 4),                   \
                       wsrc + (size_t)(16 * q) * K_VOX);                       \
        cp_async16(wsb + WS_F * 4 + wdoff, gbase + (IT) * KC);                 \
        cp_commit();                                                           \
    } while (0)
    // NOTE: wbase already contains the rb row offset; q adds 16-row strides,
    // so global row = otile + rb + 16q matches smem row rb + 16q.

    ISSUE(0, 0);
    ISSUE(1, 1);

    int st = 0, wst = 2;

    for (int it = 0; it < NITER; it++) {
        if (it + 1 < NITER) cp_wait1(); else cp_wait0();
        __syncthreads();
        if (it + 2 < NITER) {
            ISSUE(it + 2, wst);
            wst = (wst == 2) ? 0 : wst + 1;
        }

        const float* ws = smem + st * STAGE_F;
        const float* gs = ws + WS_F;
        st = (st == 2) ? 0 : st + 1;

#pragma unroll
        for (int kk = 0; kk < 2; kk++) {
            int kb = (kq + kk * 4) * 8 + lt;
            const float* ga = &gs[lg * WSTRIDE + kb];
            uint32_t a0 = __float_as_uint(ga[0]);
            uint32_t a1 = __float_as_uint(ga[8 * WSTRIDE]);
            uint32_t a2 = __float_as_uint(ga[4]);
            uint32_t a3 = __float_as_uint(ga[8 * WSTRIDE + 4]);
            const float* wb = &ws[(ohalf + lg) * WSTRIDE + kb];
#pragma unroll
            for (int j = 0; j < 8; j++) {
                uint32_t b0 = tf32_rna(wb[j * 8 * WSTRIDE]);
                uint32_t b1 = tf32_rna(wb[j * 8 * WSTRIDE + 4]);
                mma_tf32(acc[j], a0, a1, a2, a3, b0, b1);
            }
        }
    }
#undef ISSUE

    // ---- kq reduction in smem, then atomics ----
    __syncthreads();
    const int RS = 132;
    float* red = smem;   // 4*16*132 = 8448 floats, fits in stage 0
#pragma unroll
    for (int j = 0; j < 8; j++) {
        int o = ohalf + j * 8 + lt * 2;
        float* r0 = &red[(kq * MT + lg) * RS + o];
        r0[0] = acc[j][0];
        r0[1] = acc[j][1];
        r0[8 * RS] = acc[j][2];
        r0[8 * RS + 1] = acc[j][3];
    }
    __syncthreads();
    int rm = tid >> 4;
    int oc = (tid & 15) * 8;
    if (rm < rows) {
        float sum[8];
#pragma unroll
        for (int i = 0; i < 8; i++) sum[i] = 0.f;
#pragma unroll
        for (int q = 0; q < 4; q++) {
            const float* rp = &red[(q * MT + rm) * RS + oc];
#pragma unroll
            for (int i = 0; i < 8; i++) sum[i] += rp[i];
        }
        int b = g_order[off + mtile + rm];
        float* op = &out[b * OUT_DIMN + otile + oc];
#pragma unroll
        for (int i = 0; i < 8; i++) atomicAdd(op + i, sum[i]);
    }
}

extern "C" void kernel_launch(void* const* d_in, const int* in_sizes, int n_in,
                              void* d_out, int out_size) {
    (void)in_sizes; (void)n_in; (void)out_size;
    const void*  idp  = d_in[0];
    const float* fmri = (const float*)d_in[1];
    const int*   idx  = (const int*)d_in[2];
    const float* Wt   = (const float*)d_in[3];
    const float* bias = (const float*)d_in[4];
    float* out = (float*)d_out;

    static bool attr_set = false;
    if (!attr_set) {
        cudaFuncSetAttribute(gemm_kernel,
                             cudaFuncAttributeMaxDynamicSharedMemorySize, SMEM_BYTES);
        attr_set = true;
    }

    setup_kernel<<<1, 32>>>(idp);
    init_out_kernel<<<(B_BATCH * OUT_DIMN + 255) / 256, 256>>>(out, bias);
    gather_kernel<<<dim3((K_VOX + 255) / 256, B_BATCH), 256>>>(fmri, idx);
    gemm_kernel<<<dim3(OUT_DIMN / OT, 16, KSPLIT), 256, SMEM_BYTES>>>(Wt, out);
}

// round 12
// speedup vs baseline: 2.5797x; 1.0934x over previous
#include <cuda_runtime.h>
#include <cstdint>

#define S_SUBJ   4
#define B_BATCH  64
#define K_VOX    40000
#define OUT_DIMN 768
#define V_VOX    (64*64*48)

#define OT      128          // outputs per block tile
#define MT      16           // samples per block tile (= MMA M)
#define KSPLIT  50
#define KCHUNK  800          // 40000 / 50
#define KC      32           // K per smem chunk
#define NITER   (KCHUNK/KC)  // 25
#define STAGES  4

#define WSTRIDE 36           // padded row stride (floats) -> conflict-free LDS.32
#define WS_F    (OT*WSTRIDE) // 4608 floats
#define GS_F    (MT*WSTRIDE) // 576 floats
#define STAGE_F (WS_F+GS_F)  // 5184 floats
#define STAGE_B (STAGE_F*4)  // 20736 B
#define SMEM_BYTES (STAGES*STAGE_B)   // 82944 B -> 2 blocks/SM

// -------- device scratch (allocation-free per harness rules) --------
__device__ float g_G[(size_t)B_BATCH * K_VOX];
__device__ int   g_subj[B_BATCH];
__device__ int   g_order[B_BATCH];
__device__ int   g_slotsubj[B_BATCH];
__device__ int   g_off[S_SUBJ + 1];

// -------- 1) grouping + dtype detection --------
__global__ void setup_kernel(const void* idp) {
    if (threadIdx.x != 0) return;
    const int* w = (const int*)idp;
    bool is64 = true;
    for (int i = 1; i < B_BATCH; i += 2) {
        if (w[i] != 0) { is64 = false; break; }
    }
    int subj[B_BATCH];
    for (int b = 0; b < B_BATCH; b++) {
        int s = is64 ? w[2 * b] : w[b];
        subj[b] = s;
        g_subj[b] = s;
    }
    int cnt[S_SUBJ];
    for (int s = 0; s < S_SUBJ; s++) cnt[s] = 0;
    for (int b = 0; b < B_BATCH; b++) cnt[subj[b]]++;
    int off = 0, pos[S_SUBJ];
    for (int s = 0; s < S_SUBJ; s++) { g_off[s] = off; pos[s] = off; off += cnt[s]; }
    g_off[S_SUBJ] = off;
    for (int b = 0; b < B_BATCH; b++) {
        int s = subj[b];
        int p = pos[s]++;
        g_order[p] = b;
        g_slotsubj[p] = s;
    }
}

// -------- 2) out = bias[subj[b]] --------
__global__ void init_out_kernel(float* out, const float* bias) {
    int i = blockIdx.x * blockDim.x + threadIdx.x;
    if (i >= B_BATCH * OUT_DIMN) return;
    int b = i / OUT_DIMN;
    int o = i - b * OUT_DIMN;
    out[i] = bias[g_subj[b] * OUT_DIMN + o];
}

// -------- 3) gather (pre-rounds G to tf32-RNA: A-side MMA truncation exact) ----
__global__ void gather_kernel(const float* __restrict__ fmri, const int* __restrict__ idx) {
    int slot = blockIdx.y;
    int k = blockIdx.x * blockDim.x + threadIdx.x;
    if (k >= K_VOX) return;
    int b = g_order[slot];
    int s = g_slotsubj[slot];
    float v = fmri[(size_t)b * V_VOX + idx[s * K_VOX + k]];
    uint32_t bits;
    asm("cvt.rna.tf32.f32 %0, %1;" : "=r"(bits) : "f"(v));
    g_G[(size_t)slot * K_VOX + k] = __uint_as_float(bits);
}

// -------- asm helpers --------
__device__ __forceinline__ void cp_async16(uint32_t smem_addr, const void* gptr) {
    asm volatile("cp.async.cg.shared.global [%0], [%1], 16;" :: "r"(smem_addr), "l"(gptr));
}
__device__ __forceinline__ void cp_commit() { asm volatile("cp.async.commit_group;"); }
__device__ __forceinline__ void cp_wait2() { asm volatile("cp.async.wait_group 2;"); }
__device__ __forceinline__ void cp_wait1() { asm volatile("cp.async.wait_group 1;"); }
__device__ __forceinline__ void cp_wait0() { asm volatile("cp.async.wait_group 0;"); }
__device__ __forceinline__ uint32_t tf32_rna(float f) {
    uint32_t r;
    asm("cvt.rna.tf32.f32 %0, %1;" : "=r"(r) : "f"(f));
    return r;
}
__device__ __forceinline__ void mma_tf32(float* c, uint32_t a0, uint32_t a1,
                                         uint32_t a2, uint32_t a3,
                                         uint32_t b0, uint32_t b1) {
    asm volatile(
        "mma.sync.aligned.m16n8k8.row.col.f32.tf32.tf32.f32 "
        "{%0,%1,%2,%3}, {%4,%5,%6,%7}, {%8,%9}, {%0,%1,%2,%3};"
        : "+f"(c[0]), "+f"(c[1]), "+f"(c[2]), "+f"(c[3])
        : "r"(a0), "r"(a1), "r"(a2), "r"(a3), "r"(b0), "r"(b1));
}

// -------- 4) grouped GEMM via mma.sync tf32 (HMMA) --------
// OT=128 x MT=16 x KCHUNK(800). Warp w: o-half (w&1)*64, k-step kq=w>>1.
// 4-stage cp.async pipeline (depth 3), 2 blocks/SM. Tail waits graduated:
//   pending 3 -> wait2, pending 2 (it==NITER-2) -> wait1, last -> wait0.
__global__ void __launch_bounds__(256, 2) gemm_kernel(const float* __restrict__ Wt,
                                                      float* __restrict__ out) {
    extern __shared__ __align__(16) float smem[];

    int tid = threadIdx.x;
    int warp = tid >> 5;
    int lane = tid & 31;

    int s = blockIdx.y >> 2;
    int mtile = (blockIdx.y & 3) * MT;
    int off = g_off[s];
    int count = g_off[s + 1] - off;
    int rows = count - mtile;
    if (rows <= 0) return;
    if (rows > MT) rows = MT;

    int otile = blockIdx.x * OT;
    size_t k0 = (size_t)blockIdx.z * KCHUNK;

    uint32_t smem_b;
    asm("{ .reg .u64 t; cvta.to.shared.u64 t, %1; cvt.u32.u64 %0, t; }"
        : "=r"(smem_b) : "l"(smem));

    // ---- staging map: thread -> cell (t&7), row base (t>>3 : 0..31) ----
    int cell = tid & 7;
    int rb = tid >> 3;                  // 0..31
    const float* wbase = Wt + (size_t)(s * OUT_DIMN + otile + rb) * K_VOX + k0 + cell * 4;
    int mglob = mtile + rb;             // G row (only rb<16 issues G)
    int slot = off + (mglob < count ? mglob : count - 1);
    const float* gbase = g_G + (size_t)slot * K_VOX + k0 + cell * 4;
    uint32_t wdoff = rb * (WSTRIDE * 4) + cell * 16;

    // ---- compute map ----
    int ohalf = (warp & 1) * 64;
    int kq = warp >> 1;                 // k8-step 0..3
    int lg = lane >> 2;                 // 0..7
    int lt = lane & 3;                  // 0..3

    float acc[8][4];
#pragma unroll
    for (int j = 0; j < 8; j++)
#pragma unroll
        for (int r = 0; r < 4; r++) acc[j][r] = 0.f;

#define ISSUE(IT, ST)                                                          \
    do {                                                                       \
        uint32_t wsb = smem_b + (ST) * STAGE_B;                                \
        const float* wsrc = wbase + (IT) * KC;                                 \
        _Pragma("unroll")                                                      \
        for (int q = 0; q < 4; q++)                                            \
            cp_async16(wsb + wdoff + q * (32 * WSTRIDE * 4),                   \
                       wsrc + (size_t)(32 * q) * K_VOX);                       \
        if (rb < MT)                                                           \
            cp_async16(wsb + WS_F * 4 + wdoff, gbase + (IT) * KC);             \
        cp_commit();                                                           \
    } while (0)
    // global W row = otile + rb + 32q  matches smem row rb + 32q.

    ISSUE(0, 0);
    ISSUE(1, 1);
    ISSUE(2, 2);

    int st = 0, wst = 3;

    for (int it = 0; it < NITER; it++) {
        // pending groups before wait: min(it+2, NITER-1) - it + 1
        if (it + 3 <= NITER)      cp_wait2();   // 3 pending -> ensure chunk it
        else if (it + 2 <= NITER) cp_wait1();   // it == NITER-2: 2 pending
        else                      cp_wait0();   // last chunk
        __syncthreads();
        if (it + 3 < NITER) {
            ISSUE(it + 3, wst);
            wst = (wst == STAGES - 1) ? 0 : wst + 1;
        }

        const float* ws = smem + st * STAGE_F;
        const float* gs = ws + WS_F;
        st = (st == STAGES - 1) ? 0 : st + 1;

        {
            int kb = kq * 8 + lt;
            const float* ga = &gs[lg * WSTRIDE + kb];
            uint32_t a0 = __float_as_uint(ga[0]);
            uint32_t a1 = __float_as_uint(ga[8 * WSTRIDE]);
            uint32_t a2 = __float_as_uint(ga[4]);
            uint32_t a3 = __float_as_uint(ga[8 * WSTRIDE + 4]);
            const float* wb = &ws[(ohalf + lg) * WSTRIDE + kb];
#pragma unroll
            for (int j = 0; j < 8; j++) {
                uint32_t b0 = tf32_rna(wb[j * 8 * WSTRIDE]);
                uint32_t b1 = tf32_rna(wb[j * 8 * WSTRIDE + 4]);
                mma_tf32(acc[j], a0, a1, a2, a3, b0, b1);
            }
        }
    }
#undef ISSUE

    // ---- kq reduction in smem, then atomics ----
    __syncthreads();
    const int RS = 132;
    float* red = smem;   // 4*16*132 = 8448 floats (< STAGE_F*STAGES)
#pragma unroll
    for (int j = 0; j < 8; j++) {
        int o = ohalf + j * 8 + lt * 2;
        float* r0 = &red[(kq * MT + lg) * RS + o];
        r0[0] = acc[j][0];
        r0[1] = acc[j][1];
        r0[8 * RS] = acc[j][2];
        r0[8 * RS + 1] = acc[j][3];
    }
    __syncthreads();
    int rm = tid >> 4;
    int oc = (tid & 15) * 8;
    if (rm < rows) {
        float sum[8];
#pragma unroll
        for (int i = 0; i < 8; i++) sum[i] = 0.f;
#pragma unroll
        for (int q = 0; q < 4; q++) {
            const float* rp = &red[(q * MT + rm) * RS + oc];
#pragma unroll
            for (int i = 0; i < 8; i++) sum[i] += rp[i];
        }
        int b = g_order[off + mtile + rm];
        float* op = &out[b * OUT_DIMN + otile + oc];
#pragma unroll
        for (int i = 0; i < 8; i++) atomicAdd(op + i, sum[i]);
    }
}

extern "C" void kernel_launch(void* const* d_in, const int* in_sizes, int n_in,
                              void* d_out, int out_size) {
    (void)in_sizes; (void)n_in; (void)out_size;
    const void*  idp  = d_in[0];
    const float* fmri = (const float*)d_in[1];
    const int*   idx  = (const int*)d_in[2];
    const float* Wt   = (const float*)d_in[3];
    const float* bias = (const float*)d_in[4];
    float* out = (float*)d_out;

    static bool attr_set = false;
    if (!attr_set) {
        cudaFuncSetAttribute(gemm_kernel,
                             cudaFuncAttributeMaxDynamicSharedMemorySize, SMEM_BYTES);
        attr_set = true;
    }

    setup_kernel<<<1, 32>>>(idp);
    init_out_kernel<<<(B_BATCH * OUT_DIMN + 255) / 256, 256>>>(out, bias);
    gather_kernel<<<dim3((K_VOX + 255) / 256, B_BATCH), 256>>>(fmri, idx);
    gemm_kernel<<<dim3(OUT_DIMN / OT, 16, KSPLIT), 256, SMEM_BYTES>>>(Wt, out);
}